// round 13
// baseline (speedup 1.0000x reference)
#include <cuda_runtime.h>
#include <cstdint>
#include <math.h>

#define THREADS 512
#define ROWS_PER_BLOCK 64
#define NF 128
#define NG 64
#define NM 3
#define PAD 129
#define CHUNKS 8
#define GPC 8

#define HALF_LOG_2PI 0.9189385332046727f
#define L2E 1.4426950408889634f
#define LN2 0.6931471805599453f

__device__ __forceinline__ float ex2f(float x) {
    float y; asm("ex2.approx.ftz.f32 %0, %1;" : "=f"(y) : "f"(x)); return y;
}
__device__ __forceinline__ float lg2f(float x) {
    float y; asm("lg2.approx.ftz.f32 %0, %1;" : "=f"(y) : "f"(x)); return y;
}

__global__ void __launch_bounds__(THREADS, 2)
spn_kernel(const float* __restrict__ x,
           const int* __restrict__ perm,
           const float* __restrict__ means,
           const float* __restrict__ stds,
           const float* __restrict__ sumw,
           float* __restrict__ out,
           int B)
{
    // Static smem: 4096 + 512 + 33024 + 2048 = 39680 B -> 2 blocks/SM
    __shared__ float4 sPack[NG * 4];
    __shared__ int2   sIdx[NG];
    __shared__ float  sx[ROWS_PER_BLOCK * PAD];
    __shared__ float  sRed[CHUNKS * ROWS_PER_BLOCK];

    const int t    = threadIdx.x;
    const int w    = t >> 5;       // warp id 0..15
    const int lane = t & 31;

    // ---- Phase A: threads 0..63 fold params (+ log-softmax) into quadratic
    // coefficients; overlaps the other 14 warps' tile LDG latency.
    if (t < NG) {
        const int g  = t;
        const int j0 = 2 * g, j1 = 2 * g + 1;
        sIdx[g] = make_int2(perm[j0], perm[j1]);

        float sw0 = sumw[g * 3 + 0];
        float sw1 = sumw[g * 3 + 1];
        float sw2 = sumw[g * 3 + 2];
        float mw  = fmaxf(sw0, fmaxf(sw1, sw2));
        float lse = mw + logf(expf(sw0 - mw) + expf(sw1 - mw) + expf(sw2 - mw));

        float C[3];
        #pragma unroll
        for (int m = 0; m < NM; ++m) {
            float mu0 = means[j0 * 3 + m], sd0 = stds[j0 * 3 + m];
            float mu1 = means[j1 * 3 + m], sd1 = stds[j1 * 3 + m];
            float is0 = 1.0f / sd0, is1 = 1.0f / sd1;
            float is0sq = is0 * is0, is1sq = is1 * is1;
            float a0 = -0.5f * is0sq, b0 = mu0 * is0sq;
            float c0 = -0.5f * mu0 * mu0 * is0sq - logf(sd0) - HALF_LOG_2PI;
            float a1 = -0.5f * is1sq, b1 = mu1 * is1sq;
            float c1 = -0.5f * mu1 * mu1 * is1sq - logf(sd1) - HALF_LOG_2PI;
            float logw = (m == 0 ? sw0 : (m == 1 ? sw1 : sw2)) - lse;
            C[m] = (c0 + c1 + logw) * L2E;
            sPack[g * 4 + m] = make_float4(a0 * L2E, b0 * L2E, a1 * L2E, b1 * L2E);
        }
        sPack[g * 4 + 3] = make_float4(C[0], C[1], C[2], 0.0f);
    }

    // ---- Phase B: stage x tile. Warp w fills rows 4w..4w+3; per warp-instr
    // 4 rows x 8 col-quads: STS bank = (r + 4b + j) mod 32, a+4b perm of 0..31.
    const int rowBase = blockIdx.x * ROWS_PER_BLOCK;
    {
        const float4* xg = reinterpret_cast<const float4*>(x)
                         + (long long)rowBase * (NF / 4);
        const int a = lane >> 3, b = lane & 7;
        const int r = w * 4 + a;
        #pragma unroll
        for (int s = 0; s < 4; ++s) {
            float4 v4 = xg[r * 32 + b + 8 * s];
            float* dst = &sx[r * PAD + 4 * (b + 8 * s)];
            dst[0] = v4.x; dst[1] = v4.y; dst[2] = v4.z; dst[3] = v4.w;
        }
    }
    __syncthreads();

    // ---- Phase C: warp w handles chunk w>>1 (8 groups) for row lane + 32*(w&1).
    const int chunk = w >> 1;
    const int row   = lane + 32 * (w & 1);
    const float* xr = &sx[row * PAD];

    // per-warp loop-invariant gather columns (broadcast LDS)
    int ucol[GPC], vcol[GPC];
    #pragma unroll
    for (int i = 0; i < GPC; ++i) {
        int2 uv = sIdx[chunk * GPC + i];
        ucol[i] = uv.x;
        vcol[i] = uv.y;
    }

    float accM = 0.0f, prod = 1.0f;

    #pragma unroll
    for (int i = 0; i < GPC; ++i) {
        const int g = chunk * GPC + i;
        float4 k0 = sPack[g * 4 + 0];
        float4 k1 = sPack[g * 4 + 1];
        float4 k2 = sPack[g * 4 + 2];
        float4 kc = sPack[g * 4 + 3];

        float x0 = xr[ucol[i]];
        float x1 = xr[vcol[i]];

        float p0 = fmaf(fmaf(k0.z, x1, k0.w), x1, fmaf(fmaf(k0.x, x0, k0.y), x0, kc.x));
        float p1 = fmaf(fmaf(k1.z, x1, k1.w), x1, fmaf(fmaf(k1.x, x0, k1.y), x0, kc.y));
        float p2 = fmaf(fmaf(k2.z, x1, k2.w), x1, fmaf(fmaf(k2.x, x0, k2.y), x0, kc.z));

        float hi = fmaxf(p0, p1), lo = fminf(p0, p1);
        float mx = fmaxf(hi, p2), m2 = fminf(hi, p2);
        float s  = (1.0f + ex2f(lo - mx)) + ex2f(m2 - mx);
        accM += mx;
        prod *= s;
    }

    // one lg2 per chunk per row (prod in [1, 3^8])
    sRed[chunk * ROWS_PER_BLOCK + row] = accM + lg2f(prod);
    __syncthreads();

    // ---- Phase D: threads 0..63 reduce 8 chunk partials per row; store
    if (t < ROWS_PER_BLOCK) {
        float v = 0.0f;
        #pragma unroll
        for (int c = 0; c < CHUNKS; ++c)
            v += sRed[c * ROWS_PER_BLOCK + t];
        int gRow = rowBase + t;
        if (gRow < B) out[gRow] = v * LN2;
    }
}

extern "C" void kernel_launch(void* const* d_in, const int* in_sizes, int n_in,
                              void* d_out, int out_size)
{
    const float* x     = (const float*)d_in[0];
    const int*   perm  = (const int*)d_in[1];
    const float* means = (const float*)d_in[2];
    const float* stds  = (const float*)d_in[3];
    const float* sumw  = (const float*)d_in[4];
    float* out = (float*)d_out;

    int B = in_sizes[0] / NF;

    dim3 grid((B + ROWS_PER_BLOCK - 1) / ROWS_PER_BLOCK);
    spn_kernel<<<grid, THREADS>>>(x, perm, means, stds, sumw, out, B);
}

// round 14
// speedup vs baseline: 1.3907x; 1.3907x over previous
#include <cuda_runtime.h>
#include <cstdint>
#include <math.h>

#define THREADS 256
#define ROWS_PER_BLOCK 64
#define NF 128
#define NG 64
#define NM 3
#define PAD 129
#define CHUNKS 8
#define GPC 8

#define HALF_LOG_2PI 0.9189385332046727f
#define L2E 1.4426950408889634f
#define LN2 0.6931471805599453f

__device__ float4 gPack[NG * 4];
__device__ int2   gIdx[NG];

__device__ __forceinline__ float ex2f(float x) {
    float y; asm("ex2.approx.ftz.f32 %0, %1;" : "=f"(y) : "f"(x)); return y;
}
__device__ __forceinline__ float lg2f(float x) {
    float y; asm("lg2.approx.ftz.f32 %0, %1;" : "=f"(y) : "f"(x)); return y;
}

// ---- Prep kernel: fold params (+ log-softmax) into per-group quadratic coeffs.
// Fast-math transcendentals (MUFU): coefficient accuracy ~1e-6 rel, ample.
__global__ void spn_prep_kernel(const int* __restrict__ perm,
                                const float* __restrict__ means,
                                const float* __restrict__ stds,
                                const float* __restrict__ sumw)
{
    const int g = threadIdx.x;
    if (g >= NG) return;
    const int j0 = 2 * g, j1 = 2 * g + 1;
    gIdx[g] = make_int2(perm[j0], perm[j1]);

    float sw0 = sumw[g * 3 + 0];
    float sw1 = sumw[g * 3 + 1];
    float sw2 = sumw[g * 3 + 2];
    float mw  = fmaxf(sw0, fmaxf(sw1, sw2));
    float lse = mw + LN2 * lg2f(ex2f((sw0 - mw) * L2E) + ex2f((sw1 - mw) * L2E)
                              + ex2f((sw2 - mw) * L2E));

    float C[3];
    #pragma unroll
    for (int m = 0; m < NM; ++m) {
        float mu0 = means[j0 * 3 + m], sd0 = stds[j0 * 3 + m];
        float mu1 = means[j1 * 3 + m], sd1 = stds[j1 * 3 + m];
        float is0 = 1.0f / sd0, is1 = 1.0f / sd1;
        float is0sq = is0 * is0, is1sq = is1 * is1;
        float a0 = -0.5f * is0sq, b0 = mu0 * is0sq;
        float c0 = -0.5f * mu0 * mu0 * is0sq - LN2 * lg2f(sd0) - HALF_LOG_2PI;
        float a1 = -0.5f * is1sq, b1 = mu1 * is1sq;
        float c1 = -0.5f * mu1 * mu1 * is1sq - LN2 * lg2f(sd1) - HALF_LOG_2PI;
        float logw = (m == 0 ? sw0 : (m == 1 ? sw1 : sw2)) - lse;
        C[m] = (c0 + c1 + logw) * L2E;
        gPack[g * 4 + m] = make_float4(a0 * L2E, b0 * L2E, a1 * L2E, b1 * L2E);
    }
    gPack[g * 4 + 3] = make_float4(C[0], C[1], C[2], 0.0f);
}

__global__ void __launch_bounds__(THREADS, 3)
spn_kernel(const float* __restrict__ x,
           float* __restrict__ out,
           int B)
{
    // Static smem: 4096 + 512 + 33024 + 2048 = 39680 B
    __shared__ float4 sPack[NG * 4];
    __shared__ int2   sIdx[NG];
    __shared__ float  sx[ROWS_PER_BLOCK * PAD];
    __shared__ float  sRed[CHUNKS * ROWS_PER_BLOCK];

    const int t    = threadIdx.x;
    const int w    = t >> 5;       // warp id = group chunk
    const int lane = t & 31;

    // coefficients into smem (once per block)
    sPack[t] = gPack[t];
    if (t < NG) sIdx[t] = gIdx[t];

    // ---- Fill: conflict-free. Per warp-instr 4 rows x 8 col-quads,
    // STS bank = (r + 4b + j) mod 32, a+4b a permutation of 0..31.
    const int rowBase = blockIdx.x * ROWS_PER_BLOCK;
    {
        const float4* xg = reinterpret_cast<const float4*>(x)
                         + (long long)rowBase * (NF / 4);
        const int a = lane >> 3, b = lane & 7;
        #pragma unroll
        for (int pass = 0; pass < 2; ++pass) {
            const int r = pass * 32 + w * 4 + a;
            #pragma unroll
            for (int s = 0; s < 4; ++s) {
                float4 v4 = xg[r * 32 + b + 8 * s];
                float* dst = &sx[r * PAD + 4 * (b + 8 * s)];
                dst[0] = v4.x; dst[1] = v4.y; dst[2] = v4.z; dst[3] = v4.w;
            }
        }
    }
    __syncthreads();

    // per-warp loop-invariant gather columns (broadcast LDS)
    int ucol[GPC], vcol[GPC];
    #pragma unroll
    for (int i = 0; i < GPC; ++i) {
        int2 uv = sIdx[w * GPC + i];
        ucol[i] = uv.x;
        vcol[i] = uv.y;
    }

    // ---- Compute: warp handles its 8 groups; lane covers rows lane, lane+32.
    // 1-deep software pipeline: iteration i's FMA/MUFU tail hides the LDS of
    // iteration i+1's coefficients and gathers (85-reg budget gives room).
    const float* xrA = &sx[lane * PAD];
    const float* xrB = &sx[(lane + 32) * PAD];

    float accMA = 0.0f, prodA = 1.0f;
    float accMB = 0.0f, prodB = 1.0f;

    const int gB = w * GPC;

    // prime iteration 0
    float4 k0 = sPack[gB * 4 + 0];
    float4 k1 = sPack[gB * 4 + 1];
    float4 k2 = sPack[gB * 4 + 2];
    float4 kc = sPack[gB * 4 + 3];
    float x0a = xrA[ucol[0]], x1a = xrA[vcol[0]];
    float x0b = xrB[ucol[0]], x1b = xrB[vcol[0]];

    #pragma unroll
    for (int i = 0; i < GPC; ++i) {
        // prefetch iteration i+1 (wraps harmlessly on last)
        const int j  = (i + 1) & (GPC - 1);
        const int gn = gB + j;
        float4 n0 = sPack[gn * 4 + 0];
        float4 n1 = sPack[gn * 4 + 1];
        float4 n2 = sPack[gn * 4 + 2];
        float4 nc = sPack[gn * 4 + 3];
        float nx0a = xrA[ucol[j]], nx1a = xrA[vcol[j]];
        float nx0b = xrB[ucol[j]], nx1b = xrB[vcol[j]];

        // Row A
        {
            float p0 = fmaf(fmaf(k0.z, x1a, k0.w), x1a, fmaf(fmaf(k0.x, x0a, k0.y), x0a, kc.x));
            float p1 = fmaf(fmaf(k1.z, x1a, k1.w), x1a, fmaf(fmaf(k1.x, x0a, k1.y), x0a, kc.y));
            float p2 = fmaf(fmaf(k2.z, x1a, k2.w), x1a, fmaf(fmaf(k2.x, x0a, k2.y), x0a, kc.z));
            float hi = fmaxf(p0, p1), lo = fminf(p0, p1);
            float mx = fmaxf(hi, p2), m2 = fminf(hi, p2);
            float s  = (1.0f + ex2f(lo - mx)) + ex2f(m2 - mx);
            accMA += mx;
            prodA *= s;
        }
        // Row B
        {
            float p0 = fmaf(fmaf(k0.z, x1b, k0.w), x1b, fmaf(fmaf(k0.x, x0b, k0.y), x0b, kc.x));
            float p1 = fmaf(fmaf(k1.z, x1b, k1.w), x1b, fmaf(fmaf(k1.x, x0b, k1.y), x0b, kc.y));
            float p2 = fmaf(fmaf(k2.z, x1b, k2.w), x1b, fmaf(fmaf(k2.x, x0b, k2.y), x0b, kc.z));
            float hi = fmaxf(p0, p1), lo = fminf(p0, p1);
            float mx = fmaxf(hi, p2), m2 = fminf(hi, p2);
            float s  = (1.0f + ex2f(lo - mx)) + ex2f(m2 - mx);
            accMB += mx;
            prodB *= s;
        }

        k0 = n0; k1 = n1; k2 = n2; kc = nc;
        x0a = nx0a; x1a = nx1a; x0b = nx0b; x1b = nx1b;
    }

    // one lg2 per chunk per row (prod in [1, 3^8])
    sRed[w * ROWS_PER_BLOCK + lane]      = accMA + lg2f(prodA);
    sRed[w * ROWS_PER_BLOCK + lane + 32] = accMB + lg2f(prodB);
    __syncthreads();

    // ---- reduce 8 chunk partials per row; store
    if (t < ROWS_PER_BLOCK) {
        float v = 0.0f;
        #pragma unroll
        for (int c = 0; c < CHUNKS; ++c)
            v += sRed[c * ROWS_PER_BLOCK + t];
        int gRow = rowBase + t;
        if (gRow < B) out[gRow] = v * LN2;
    }
}

extern "C" void kernel_launch(void* const* d_in, const int* in_sizes, int n_in,
                              void* d_out, int out_size)
{
    const float* x     = (const float*)d_in[0];
    const int*   perm  = (const int*)d_in[1];
    const float* means = (const float*)d_in[2];
    const float* stds  = (const float*)d_in[3];
    const float* sumw  = (const float*)d_in[4];
    float* out = (float*)d_out;

    int B = in_sizes[0] / NF;

    spn_prep_kernel<<<1, 64>>>(perm, means, stds, sumw);

    dim3 grid((B + ROWS_PER_BLOCK - 1) / ROWS_PER_BLOCK);
    spn_kernel<<<grid, THREADS>>>(x, out, B);
}

// round 15
// speedup vs baseline: 1.4016x; 1.0078x over previous
#include <cuda_runtime.h>
#include <cstdint>
#include <math.h>

#define THREADS 256
#define ROWS_PER_BLOCK 64
#define NF 128
#define NG 64
#define NM 3
#define PAD 129
#define CHUNKS 8
#define GPC 8

#define HALF_LOG_2PI 0.9189385332046727f
#define L2E 1.4426950408889634f
#define LN2 0.6931471805599453f

__device__ float4 gPack[NG * 4];
__device__ int2   gIdx[NG];

__device__ __forceinline__ float ex2f(float x) {
    float y; asm("ex2.approx.ftz.f32 %0, %1;" : "=f"(y) : "f"(x)); return y;
}
__device__ __forceinline__ float lg2f(float x) {
    float y; asm("lg2.approx.ftz.f32 %0, %1;" : "=f"(y) : "f"(x)); return y;
}

// ---- Prep kernel: fold params (+ log-softmax) into per-group quadratic coeffs.
// Fast-math transcendentals (MUFU): coefficient accuracy ~1e-6 rel, ample.
__global__ void spn_prep_kernel(const int* __restrict__ perm,
                                const float* __restrict__ means,
                                const float* __restrict__ stds,
                                const float* __restrict__ sumw)
{
    const int g = threadIdx.x;
    if (g >= NG) return;
    const int j0 = 2 * g, j1 = 2 * g + 1;
    gIdx[g] = make_int2(perm[j0], perm[j1]);

    float sw0 = sumw[g * 3 + 0];
    float sw1 = sumw[g * 3 + 1];
    float sw2 = sumw[g * 3 + 2];
    float mw  = fmaxf(sw0, fmaxf(sw1, sw2));
    float lse = mw + LN2 * lg2f(ex2f((sw0 - mw) * L2E) + ex2f((sw1 - mw) * L2E)
                              + ex2f((sw2 - mw) * L2E));

    float C[3];
    #pragma unroll
    for (int m = 0; m < NM; ++m) {
        float mu0 = means[j0 * 3 + m], sd0 = stds[j0 * 3 + m];
        float mu1 = means[j1 * 3 + m], sd1 = stds[j1 * 3 + m];
        float is0 = 1.0f / sd0, is1 = 1.0f / sd1;
        float is0sq = is0 * is0, is1sq = is1 * is1;
        float a0 = -0.5f * is0sq, b0 = mu0 * is0sq;
        float c0 = -0.5f * mu0 * mu0 * is0sq - LN2 * lg2f(sd0) - HALF_LOG_2PI;
        float a1 = -0.5f * is1sq, b1 = mu1 * is1sq;
        float c1 = -0.5f * mu1 * mu1 * is1sq - LN2 * lg2f(sd1) - HALF_LOG_2PI;
        float logw = (m == 0 ? sw0 : (m == 1 ? sw1 : sw2)) - lse;
        C[m] = (c0 + c1 + logw) * L2E;
        gPack[g * 4 + m] = make_float4(a0 * L2E, b0 * L2E, a1 * L2E, b1 * L2E);
    }
    gPack[g * 4 + 3] = make_float4(C[0], C[1], C[2], 0.0f);
}

__global__ void __launch_bounds__(THREADS, 4)
spn_kernel(const float* __restrict__ x,
           float* __restrict__ out,
           int B)
{
    // Static smem: 4096 + 512 + 33024 + 2048 = 39680 B
    __shared__ float4 sPack[NG * 4];
    __shared__ int2   sIdx[NG];
    __shared__ float  sx[ROWS_PER_BLOCK * PAD];
    __shared__ float  sRed[CHUNKS * ROWS_PER_BLOCK];

    const int t    = threadIdx.x;
    const int w    = t >> 5;       // warp id = group chunk
    const int lane = t & 31;

    // coefficients into smem (once per block)
    sPack[t] = gPack[t];
    if (t < NG) sIdx[t] = gIdx[t];

    // ---- Fill: conflict-free. Per warp-instr 4 rows x 8 col-quads,
    // STS bank = (r + 4b + j) mod 32, a+4b a permutation of 0..31.
    const int rowBase = blockIdx.x * ROWS_PER_BLOCK;
    {
        const float4* xg = reinterpret_cast<const float4*>(x)
                         + (long long)rowBase * (NF / 4);
        const int a = lane >> 3, b = lane & 7;
        #pragma unroll
        for (int pass = 0; pass < 2; ++pass) {
            const int r = pass * 32 + w * 4 + a;
            #pragma unroll
            for (int s = 0; s < 4; ++s) {
                float4 v4 = xg[r * 32 + b + 8 * s];
                float* dst = &sx[r * PAD + 4 * (b + 8 * s)];
                dst[0] = v4.x; dst[1] = v4.y; dst[2] = v4.z; dst[3] = v4.w;
            }
        }
    }
    __syncthreads();

    // per-warp loop-invariant gather columns (broadcast LDS)
    int ucol[GPC], vcol[GPC];
    #pragma unroll
    for (int i = 0; i < GPC; ++i) {
        int2 uv = sIdx[w * GPC + i];
        ucol[i] = uv.x;
        vcol[i] = uv.y;
    }

    // ---- Compute: warp handles its 8 groups; lane covers rows lane, lane+32.
    // Gathers conflict-free: bank = (row + col) mod 32.
    const float* xrA = &sx[lane * PAD];
    const float* xrB = &sx[(lane + 32) * PAD];

    float accMA = 0.0f, prodA = 1.0f;
    float accMB = 0.0f, prodB = 1.0f;

    #pragma unroll
    for (int i = 0; i < GPC; ++i) {
        const int g = w * GPC + i;
        float4 k0 = sPack[g * 4 + 0];
        float4 k1 = sPack[g * 4 + 1];
        float4 k2 = sPack[g * 4 + 2];
        float4 kc = sPack[g * 4 + 3];

        float x0a = xrA[ucol[i]], x1a = xrA[vcol[i]];
        float x0b = xrB[ucol[i]], x1b = xrB[vcol[i]];

        // Row A: 2 ex2 (max term folded to 1), product accumulation
        {
            float p0 = fmaf(fmaf(k0.z, x1a, k0.w), x1a, fmaf(fmaf(k0.x, x0a, k0.y), x0a, kc.x));
            float p1 = fmaf(fmaf(k1.z, x1a, k1.w), x1a, fmaf(fmaf(k1.x, x0a, k1.y), x0a, kc.y));
            float p2 = fmaf(fmaf(k2.z, x1a, k2.w), x1a, fmaf(fmaf(k2.x, x0a, k2.y), x0a, kc.z));
            float hi = fmaxf(p0, p1), lo = fminf(p0, p1);
            float mx = fmaxf(hi, p2), m2 = fminf(hi, p2);
            float s  = (1.0f + ex2f(lo - mx)) + ex2f(m2 - mx);
            accMA += mx;
            prodA *= s;
        }
        // Row B
        {
            float p0 = fmaf(fmaf(k0.z, x1b, k0.w), x1b, fmaf(fmaf(k0.x, x0b, k0.y), x0b, kc.x));
            float p1 = fmaf(fmaf(k1.z, x1b, k1.w), x1b, fmaf(fmaf(k1.x, x0b, k1.y), x0b, kc.y));
            float p2 = fmaf(fmaf(k2.z, x1b, k2.w), x1b, fmaf(fmaf(k2.x, x0b, k2.y), x0b, kc.z));
            float hi = fmaxf(p0, p1), lo = fminf(p0, p1);
            float mx = fmaxf(hi, p2), m2 = fminf(hi, p2);
            float s  = (1.0f + ex2f(lo - mx)) + ex2f(m2 - mx);
            accMB += mx;
            prodB *= s;
        }
    }

    // one lg2 per chunk per row (prod in [1, 3^8])
    sRed[w * ROWS_PER_BLOCK + lane]      = accMA + lg2f(prodA);
    sRed[w * ROWS_PER_BLOCK + lane + 32] = accMB + lg2f(prodB);
    __syncthreads();

    // ---- reduce 8 chunk partials per row; store
    if (t < ROWS_PER_BLOCK) {
        float v = 0.0f;
        #pragma unroll
        for (int c = 0; c < CHUNKS; ++c)
            v += sRed[c * ROWS_PER_BLOCK + t];
        int gRow = rowBase + t;
        if (gRow < B) out[gRow] = v * LN2;
    }
}

extern "C" void kernel_launch(void* const* d_in, const int* in_sizes, int n_in,
                              void* d_out, int out_size)
{
    const float* x     = (const float*)d_in[0];
    const int*   perm  = (const int*)d_in[1];
    const float* means = (const float*)d_in[2];
    const float* stds  = (const float*)d_in[3];
    const float* sumw  = (const float*)d_in[4];
    float* out = (float*)d_out;

    int B = in_sizes[0] / NF;

    spn_prep_kernel<<<1, 64>>>(perm, means, stds, sumw);

    dim3 grid((B + ROWS_PER_BLOCK - 1) / ROWS_PER_BLOCK);
    spn_kernel<<<grid, THREADS>>>(x, out, B);
}